// round 10
// baseline (speedup 1.0000x reference)
#include <cuda_runtime.h>

#define HH 256
#define WW 256
#define MAXSLICES 64
#define TPC 16              // CTAs (16-col tiles) per slice
#define CSTRIDE 17          // u16 row stride for g tile (odd shift: conflict-free)

// ---- device globals (allocation-free scratch / rendezvous state) ----
__device__ unsigned g_bits[MAXSLICES * (HH * WW / 32)];   // 2048 words/slice
__device__ int g_ticket[MAXSLICES];                       // monotonic, reset-free
__device__ int g_pmax[MAXSLICES][TPC];                    // overwritten each replay

// ================= K_pre: pack mask bits (bandwidth-bound, ~2.8us) ========
__global__ void __launch_bounds__(256) k_pack(const float* __restrict__ in)
{
    const int base = blockIdx.x * 2048 + threadIdx.x;
    #pragma unroll
    for (int i = 0; i < 8; i++) {
        int n = base + i * 256;
        bool m = (in[n] != 0.0f);
        unsigned b = __ballot_sync(0xffffffffu, m);
        if ((threadIdx.x & 31) == 0) g_bits[n >> 5] = b;
    }
}

__device__ __forceinline__ void spin_until(volatile int* p, int target)
{
    while (*p < target) __nanosleep(32);
}

// ================= fused: g -> exact min-plus -> rendezvous -> write =======
// CTA = (slice, 16-col tile); 256 threads = 16 cols x 16 row-groups of 16 rows.
__global__ void __launch_bounds__(256, 6)
wdt_fused(float* __restrict__ out)
{
    __shared__ unsigned       bm[HH * 8];           // 8192 B: slice bitmask; reused as d2 park
    __shared__ unsigned short gs[HH * CSTRIDE];     // 8704 B: g tile
    __shared__ int   s_red;
    __shared__ int   s_m2;
    __shared__ float s_rinv;

    const int slice = blockIdx.x >> 4;
    const int ct    = blockIdx.x & 15;
    const int t     = threadIdx.x;
    float* oslab = out + (size_t)slice * (HH * WW) + ct * 16;

    if (t == 0) s_red = 0;

    // ---- phase 1: load packed slice bitmask (vectorized, L2-resident) ----
    {
        const uint4* src4 = reinterpret_cast<const uint4*>(g_bits + slice * 2048);
        uint4* bm4 = reinterpret_cast<uint4*>(bm);
        bm4[t]       = src4[t];
        bm4[t + 256] = src4[t + 256];
    }
    __syncthreads();

    // ---- phase 2: horizontal nearest-zero distance, 64-bit scan window ----
    // wi = ct>>1 is CTA-uniform; j in [0,32). Window covers dl/dr up to 32+j /
    // 63-j, so the word-loop fallback fires only with >=33 consecutive ones
    // (probability ~2^-33 on this input) -- warp divergence eliminated.
    const int col  = t & 15;
    const int j    = (ct & 1) * 16 + col;     // bit within word
    const int wi   = ct >> 1;                 // CTA-uniform word index
    const int q0   = (t >> 4) * 16;           // this thread's 16 rows
    const unsigned long long maskL64 = (1ULL << (32 + j)) - 1ULL;       // bits < 32+j
    const unsigned long long maskR64 = ~((2ULL << j) - 1ULL);           // bits > j

    for (int r = q0; r < q0 + 16; r++) {
        const unsigned* row = bm + r * 8;
        unsigned cur = row[wi];
        int gv = 0;
        if ((cur >> j) & 1) {
            unsigned prevw = (wi > 0) ? row[wi - 1] : 0xffffffffu;  // outside: no zeros
            unsigned nextw = (wi < 7) ? row[wi + 1] : 0xffffffffu;
            unsigned long long lo = ((unsigned long long)cur << 32) | prevw;   // bit 32+j = cur[j]
            unsigned long long hi = ((unsigned long long)nextw << 32) | cur;   // bit j    = cur[j]

            int dl = 512, dr = 512;           // BIG = H + W (matches reference clamp)
            unsigned long long y = (~lo) & maskL64;
            if (y) dl = (32 + j) - (63 - __clzll(y));
            else {
                for (int k = wi - 2; k >= 0 && dl == 512; k--) {
                    unsigned iv = ~row[k];
                    if (iv) dl = j - (31 - __clz(iv)) + 32 * (wi - k);
                }
            }
            y = (~hi) & maskR64;
            if (y) dr = __ffsll(y) - 1 - j;
            else {
                for (int k = wi + 2; k < 8 && dr == 512; k++) {
                    unsigned iv = ~row[k];
                    if (iv) dr = __ffs(iv) - 1 - j + 32 * (k - wi);
                }
            }
            gv = min(dl, dr);
        }
        gs[r * CSTRIDE + col] = (unsigned short)gv;
    }
    __syncthreads();          // phase 2 done; bm is dead -> becomes the d2 park

    // ---- phase 3: exact vertical min-plus (shrinking radius) ----
    // d2[q] = min_r' g[r']^2 + (q-r')^2; start r'=q, stop when dr^2 >= best: exact.
    int colmax = 0;
    unsigned pair = 0;
    #pragma unroll
    for (int k = 0; k < 16; k++) {
        int q = q0 + k;
        int gv = gs[q * CSTRIDE + col];
        int best = gv * gv;
        for (int dd = 1; dd * dd < best; dd++) {
            int ddsq = dd * dd;
            int u = q - dd, v = q + dd;
            if (u >= 0) { int c = gs[u * CSTRIDE + col]; c = c * c + ddsq; if (c < best) best = c; }
            if (v < HH) { int c = gs[v * CSTRIDE + col]; c = c * c + ddsq; if (c < best) best = c; }
        }
        if (best > colmax) colmax = best;
        unsigned pb = (unsigned)min(best, 65535);   // exact whenever the slice has any zero
        if ((k & 1) == 0) pair = pb;
        else              bm[(k >> 1) * 256 + t] = pair | (pb << 16);
    }

    // ---- phase 4: CTA max, then TPC-way reset-free rendezvous ----
    #pragma unroll
    for (int off = 16; off; off >>= 1)
        colmax = max(colmax, __shfl_xor_sync(0xffffffffu, colmax, off));
    if ((t & 31) == 0) atomicMax(&s_red, colmax);
    __syncthreads();

    if (t == 0) {
        g_pmax[slice][ct] = s_red;                  // plain store each replay
        __threadfence();
        int tk = atomicAdd(&g_ticket[slice], 1);    // monotonic ticket
        int target = (tk & ~(TPC - 1)) + TPC;       // my replay's group of TPC
        spin_until(&g_ticket[slice], target);
        __threadfence();
        int m2 = 0;
        #pragma unroll
        for (int i = 0; i < TPC; i++) m2 = max(m2, __ldcg(&g_pmax[slice][i]));
        s_m2 = m2;
        s_rinv = (m2 > 0) ? rsqrtf((float)m2) : 0.0f;
    }
    __syncthreads();

    // ---- phase 5: normalized output, written exactly once (coalesced) ----
    const float rinv = s_rinv;
    if (s_m2 > 0) {
        #pragma unroll
        for (int i = 0; i < 8; i++) {
            unsigned w = bm[i * 256 + t];
            int q = q0 + 2 * i;
            oslab[q * WW + col]       = 1.0f - sqrtf((float)(w & 0xffffu)) * rinv;
            oslab[(q + 1) * WW + col] = 1.0f - sqrtf((float)(w >> 16)) * rinv;
        }
    } else {
        // whole slice background: dt == 0 everywhere, reference outputs dt (= 0)
        #pragma unroll
        for (int i = 0; i < 16; i++) oslab[(q0 + i) * WW + col] = 0.0f;
    }
}

extern "C" void kernel_launch(void* const* d_in, const int* in_sizes, int n_in,
                              void* d_out, int out_size)
{
    const float* in = (const float*)d_in[0];
    float* out = (float*)d_out;

    int slices = in_sizes[0] / (HH * WW);   // 48 for the reference shapes
    if (slices > MAXSLICES) slices = MAXSLICES;

    // Pin max smem carveout: 6 CTAs/SM (6 x 16.9KB = 101.5KB) never smem-limited.
    cudaFuncSetAttribute(wdt_fused, cudaFuncAttributePreferredSharedMemoryCarveout, 100);

    k_pack<<<slices * 32, 256>>>(in);
    // launch_bounds(256,6): capacity 148*6 = 888 >= grid 768 -> all CTAs
    // co-resident -> the max rendezvous cannot deadlock.
    wdt_fused<<<slices * TPC, 256>>>(out);
}

// round 11
// speedup vs baseline: 1.1664x; 1.1664x over previous
#include <cuda_runtime.h>

#define HH 256
#define WW 256
#define MAXSLICES 64
#define TPC 16              // CTAs (16-col tiles) per slice
#define CSTRIDE 17          // u16 row stride for g tile (odd shift: conflict-free)

// ---- device globals (allocation-free scratch / rendezvous state) ----
__device__ unsigned g_bits[MAXSLICES * (HH * WW / 32)];   // 2048 words/slice
__device__ int g_ticket[MAXSLICES];                       // monotonic, reset-free
__device__ int g_pmax[MAXSLICES][TPC];                    // overwritten each replay

// ================= K_pre: pack mask bits (bandwidth-bound, ~2.8us) ========
__global__ void __launch_bounds__(256) k_pack(const float* __restrict__ in)
{
    const int base = blockIdx.x * 2048 + threadIdx.x;
    #pragma unroll
    for (int i = 0; i < 8; i++) {
        int n = base + i * 256;
        bool m = (in[n] != 0.0f);
        unsigned b = __ballot_sync(0xffffffffu, m);
        if ((threadIdx.x & 31) == 0) g_bits[n >> 5] = b;
    }
}

__device__ __forceinline__ void spin_until(volatile int* p, int target)
{
    while (*p < target) __nanosleep(32);
}

// ================= fused: g -> exact min-plus -> rendezvous -> write =======
// CTA = (slice, 16-col tile); 256 threads = 16 cols x 16 row-groups of 16 rows.
__global__ void __launch_bounds__(256, 6)
wdt_fused(float* __restrict__ out)
{
    __shared__ unsigned       bm[HH * 8];           // 8192 B: slice bitmask; reused as d2 park
    __shared__ unsigned short gs[HH * CSTRIDE];     // 8704 B: g tile
    __shared__ int   s_red;
    __shared__ int   s_m2;
    __shared__ float s_rinv;

    const int slice = blockIdx.x >> 4;
    const int ct    = blockIdx.x & 15;
    const int t     = threadIdx.x;
    float* oslab = out + (size_t)slice * (HH * WW) + ct * 16;

    if (t == 0) s_red = 0;

    // ---- phase 1: load packed slice bitmask (vectorized, L2-resident) ----
    {
        const uint4* src4 = reinterpret_cast<const uint4*>(g_bits + slice * 2048);
        uint4* bm4 = reinterpret_cast<uint4*>(bm);
        bm4[t]       = src4[t];
        bm4[t + 256] = src4[t + 256];
    }
    __syncthreads();

    // ---- phase 2: horizontal nearest-zero distance via funnel-shift windows ----
    // Left:  concat (cur:prev) >> (j+1) -> first zero at dl = clz (covers d=1..31;
    //        the pixel's own 1-bit self-masks result bit 31).
    // Right: concat (next:cur) >> (j+1) -> dr = ffs (covers d=1..32).
    // Fallback (>=31 consecutive ones) has probability ~2^-31: exact serial scan.
    const int col  = t & 15;
    const int gcol = ct * 16 + col;
    const int j    = gcol & 31;
    const int wi   = gcol >> 5;               // CTA-uniform word index
    const int q0   = (t >> 4) * 16;           // this thread's 16 rows

    for (int r = q0; r < q0 + 16; r++) {
        const unsigned* row = bm + r * 8;     // broadcast LDS reads (uniform wi)
        unsigned cur = row[wi];
        int gv = 0;
        if ((cur >> j) & 1) {
            unsigned prevw = (wi > 0) ? row[wi - 1] : 0xffffffffu;  // outside: no zeros
            unsigned nextw = (wi < 7) ? row[wi + 1] : 0xffffffffu;

            int dl, dr;
            unsigned yl = ~__funnelshift_rc(prevw, cur, j + 1);
            if (yl) dl = __clz(yl);
            else {                              // zero farther than 31 left (rare)
                dl = 512;                       // BIG = H + W (matches reference clamp)
                for (int d = 32; d <= gcol && dl == 512; d++) {
                    int cc = gcol - d;
                    if (!((row[cc >> 5] >> (cc & 31)) & 1)) dl = d;
                }
            }
            unsigned yr = ~__funnelshift_rc(cur, nextw, j + 1);
            if (yr) dr = __ffs(yr);
            else {                              // zero farther than 32 right (rare)
                dr = 512;
                for (int d = 33; gcol + d < WW && dr == 512; d++) {
                    int cc = gcol + d;
                    if (!((row[cc >> 5] >> (cc & 31)) & 1)) dr = d;
                }
            }
            gv = min(dl, dr);
        }
        gs[r * CSTRIDE + col] = (unsigned short)gv;
    }
    __syncthreads();          // phase 2 done; bm is dead -> becomes the d2 park

    // ---- phase 3: exact vertical min-plus (shrinking radius) ----
    // d2[q] = min_r' g[r']^2 + (q-r')^2; start r'=q, stop when dd^2 >= best: exact.
    int colmax = 0;
    unsigned pair = 0;
    #pragma unroll
    for (int k = 0; k < 16; k++) {
        int q = q0 + k;
        int gv = gs[q * CSTRIDE + col];
        int best = gv * gv;
        for (int dd = 1; dd * dd < best; dd++) {
            int ddsq = dd * dd;
            int u = q - dd, v = q + dd;
            if (u >= 0) { int c = gs[u * CSTRIDE + col]; c = c * c + ddsq; if (c < best) best = c; }
            if (v < HH) { int c = gs[v * CSTRIDE + col]; c = c * c + ddsq; if (c < best) best = c; }
        }
        if (best > colmax) colmax = best;
        unsigned pb = (unsigned)min(best, 65535);   // exact whenever the slice has any zero
        if ((k & 1) == 0) pair = pb;
        else              bm[(k >> 1) * 256 + t] = pair | (pb << 16);
    }

    // ---- phase 4: CTA max, then TPC-way reset-free rendezvous ----
    #pragma unroll
    for (int off = 16; off; off >>= 1)
        colmax = max(colmax, __shfl_xor_sync(0xffffffffu, colmax, off));
    if ((t & 31) == 0) atomicMax(&s_red, colmax);
    __syncthreads();

    if (t == 0) {
        g_pmax[slice][ct] = s_red;                  // plain store each replay
        __threadfence();
        int tk = atomicAdd(&g_ticket[slice], 1);    // monotonic ticket
        int target = (tk & ~(TPC - 1)) + TPC;       // my replay's group of TPC
        spin_until(&g_ticket[slice], target);
        __threadfence();
        int m2 = 0;
        #pragma unroll
        for (int i = 0; i < TPC; i++) m2 = max(m2, __ldcg(&g_pmax[slice][i]));
        s_m2 = m2;
        s_rinv = (m2 > 0) ? rsqrtf((float)m2) : 0.0f;
    }
    __syncthreads();

    // ---- phase 5: normalized output, written exactly once (coalesced) ----
    const float rinv = s_rinv;
    if (s_m2 > 0) {
        #pragma unroll
        for (int i = 0; i < 8; i++) {
            unsigned w = bm[i * 256 + t];
            int q = q0 + 2 * i;
            oslab[q * WW + col]       = 1.0f - sqrtf((float)(w & 0xffffu)) * rinv;
            oslab[(q + 1) * WW + col] = 1.0f - sqrtf((float)(w >> 16)) * rinv;
        }
    } else {
        // whole slice background: dt == 0 everywhere, reference outputs dt (= 0)
        #pragma unroll
        for (int i = 0; i < 16; i++) oslab[(q0 + i) * WW + col] = 0.0f;
    }
}

extern "C" void kernel_launch(void* const* d_in, const int* in_sizes, int n_in,
                              void* d_out, int out_size)
{
    const float* in = (const float*)d_in[0];
    float* out = (float*)d_out;

    int slices = in_sizes[0] / (HH * WW);   // 48 for the reference shapes
    if (slices > MAXSLICES) slices = MAXSLICES;

    // Pin max smem carveout: 6 CTAs/SM (6 x 16.9KB = 101.5KB) never smem-limited.
    cudaFuncSetAttribute(wdt_fused, cudaFuncAttributePreferredSharedMemoryCarveout, 100);

    k_pack<<<slices * 32, 256>>>(in);
    // launch_bounds(256,6): capacity 148*6 = 888 >= grid 768 -> all CTAs
    // co-resident -> the max rendezvous cannot deadlock.
    wdt_fused<<<slices * TPC, 256>>>(out);
}

// round 12
// speedup vs baseline: 1.2947x; 1.1099x over previous
#include <cuda_runtime.h>

#define HH 256
#define WW 256
#define MAXSLICES 64
#define TPC 16              // CTAs (16-col tiles) per slice
#define CSTRIDE 17          // u16 row stride for g tile (odd shift: conflict-free)
#define LUTCAP 2176         // floats fitting in the gs region (8704 B)

// ---- device globals (allocation-free scratch / rendezvous state) ----
__device__ unsigned g_bits[MAXSLICES * (HH * WW / 32)];   // 2048 words/slice
__device__ int g_ticket[MAXSLICES];                       // monotonic, reset-free
__device__ int g_pmax[MAXSLICES][TPC];                    // overwritten each replay

// ================= K_pre: pack mask bits (bandwidth-bound, ~2.8us) ========
__global__ void __launch_bounds__(256) k_pack(const float* __restrict__ in)
{
    const int base = blockIdx.x * 2048 + threadIdx.x;
    #pragma unroll
    for (int i = 0; i < 8; i++) {
        int n = base + i * 256;
        bool m = (in[n] != 0.0f);
        unsigned b = __ballot_sync(0xffffffffu, m);
        if ((threadIdx.x & 31) == 0) g_bits[n >> 5] = b;
    }
}

__device__ __forceinline__ void spin_until(volatile int* p, int target)
{
    while (*p < target) __nanosleep(32);
}

// ================= fused: g -> exact min-plus -> rendezvous -> LUT write ===
// CTA = (slice, 16-col tile); 256 threads = 16 cols x 16 row-groups of 16 rows.
__global__ void __launch_bounds__(256, 6)
wdt_fused(float* __restrict__ out)
{
    __shared__ unsigned       bm[HH * 8];           // 8192 B: bitmask; reused as d2 park
    __shared__ unsigned short gs[HH * CSTRIDE];     // 8704 B: g tile; reused as sqrt-LUT
    __shared__ int   s_red;
    __shared__ int   s_m2;
    __shared__ float s_rinv;

    const int slice = blockIdx.x >> 4;
    const int ct    = blockIdx.x & 15;
    const int t     = threadIdx.x;
    float* oslab = out + (size_t)slice * (HH * WW) + ct * 16;

    if (t == 0) s_red = 0;

    // ---- phase 1: load packed slice bitmask (vectorized, L2-resident) ----
    {
        const uint4* src4 = reinterpret_cast<const uint4*>(g_bits + slice * 2048);
        uint4* bm4 = reinterpret_cast<uint4*>(bm);
        bm4[t]       = src4[t];
        bm4[t + 256] = src4[t + 256];
    }
    __syncthreads();

    // ---- phase 2: horizontal nearest-zero distance via funnel-shift windows ----
    const int col  = t & 15;
    const int gcol = ct * 16 + col;
    const int j    = gcol & 31;
    const int wi   = gcol >> 5;               // CTA-uniform word index
    const int q0   = (t >> 4) * 16;           // this thread's 16 rows

    for (int r = q0; r < q0 + 16; r++) {
        const unsigned* row = bm + r * 8;     // broadcast LDS reads (uniform wi)
        unsigned cur = row[wi];
        int gv = 0;
        if ((cur >> j) & 1) {
            unsigned prevw = (wi > 0) ? row[wi - 1] : 0xffffffffu;  // outside: no zeros
            unsigned nextw = (wi < 7) ? row[wi + 1] : 0xffffffffu;

            int dl, dr;
            unsigned yl = ~__funnelshift_rc(prevw, cur, j + 1);
            if (yl) dl = __clz(yl);
            else {                              // zero farther than 31 left (rare)
                dl = 512;                       // BIG = H + W (matches reference clamp)
                for (int d = 32; d <= gcol && dl == 512; d++) {
                    int cc = gcol - d;
                    if (!((row[cc >> 5] >> (cc & 31)) & 1)) dl = d;
                }
            }
            unsigned yr = ~__funnelshift_rc(cur, nextw, j + 1);
            if (yr) dr = __ffs(yr);
            else {                              // zero farther than 32 right (rare)
                dr = 512;
                for (int d = 33; gcol + d < WW && dr == 512; d++) {
                    int cc = gcol + d;
                    if (!((row[cc >> 5] >> (cc & 31)) & 1)) dr = d;
                }
            }
            gv = min(dl, dr);
        }
        gs[r * CSTRIDE + col] = (unsigned short)gv;
    }
    __syncthreads();          // phase 2 done; bm is dead -> becomes the d2 park

    // ---- phase 3: exact vertical min-plus (shrinking radius) ----
    // d2[q] = min_r' g[r']^2 + (q-r')^2; start r'=q, stop when dd^2 >= best: exact.
    int colmax = 0;
    unsigned pair = 0;
    #pragma unroll
    for (int k = 0; k < 16; k++) {
        int q = q0 + k;
        int gv = gs[q * CSTRIDE + col];
        int best = gv * gv;
        for (int dd = 1; dd * dd < best; dd++) {
            int ddsq = dd * dd;
            int u = q - dd, v = q + dd;
            if (u >= 0) { int c = gs[u * CSTRIDE + col]; c = c * c + ddsq; if (c < best) best = c; }
            if (v < HH) { int c = gs[v * CSTRIDE + col]; c = c * c + ddsq; if (c < best) best = c; }
        }
        if (best > colmax) colmax = best;
        unsigned pb = (unsigned)min(best, 65535);   // exact whenever the slice has any zero
        if ((k & 1) == 0) pair = pb;
        else              bm[(k >> 1) * 256 + t] = pair | (pb << 16);
    }

    // ---- phase 4: CTA max, then TPC-way reset-free rendezvous ----
    #pragma unroll
    for (int off = 16; off; off >>= 1)
        colmax = max(colmax, __shfl_xor_sync(0xffffffffu, colmax, off));
    if ((t & 31) == 0) atomicMax(&s_red, colmax);
    __syncthreads();          // also: all phase-3 gs reads done -> gs reusable

    if (t == 0) {
        g_pmax[slice][ct] = s_red;                  // plain store each replay
        __threadfence();
        int tk = atomicAdd(&g_ticket[slice], 1);    // monotonic ticket
        int target = (tk & ~(TPC - 1)) + TPC;       // my replay's group of TPC
        spin_until(&g_ticket[slice], target);
        __threadfence();
        int m2 = 0;
        #pragma unroll
        for (int i = 0; i < TPC; i++) m2 = max(m2, __ldcg(&g_pmax[slice][i]));
        s_m2 = m2;
        s_rinv = (m2 > 0) ? rsqrtf((float)m2) : 0.0f;
    }
    __syncthreads();

    const int   m2   = s_m2;
    const float rinv = s_rinv;
    float* lut = reinterpret_cast<float*>(gs);      // gs is dead -> LUT region

    // ---- phase 5a: build sqrt-LUT (d2 is integer; ~m2 MUFU per CTA, not 4096) ----
    if (m2 > 0 && m2 < LUTCAP) {
        for (int i = t; i <= m2; i += 256)
            lut[i] = 1.0f - sqrtf((float)i) * rinv;
    }
    __syncthreads();

    // ---- phase 5b: normalized output, written exactly once (coalesced) ----
    if (m2 > 0 && m2 < LUTCAP) {
        #pragma unroll
        for (int i = 0; i < 8; i++) {
            unsigned w = bm[i * 256 + t];           // park: d2 <= m2 -> LUT-safe
            int q = q0 + 2 * i;
            oslab[q * WW + col]       = lut[w & 0xffffu];
            oslab[(q + 1) * WW + col] = lut[w >> 16];
        }
    } else if (m2 > 0) {
        // pathological huge distances: exact per-pixel sqrt fallback
        #pragma unroll
        for (int i = 0; i < 8; i++) {
            unsigned w = bm[i * 256 + t];
            int q = q0 + 2 * i;
            oslab[q * WW + col]       = 1.0f - sqrtf((float)(w & 0xffffu)) * rinv;
            oslab[(q + 1) * WW + col] = 1.0f - sqrtf((float)(w >> 16)) * rinv;
        }
    } else {
        // whole slice background: dt == 0 everywhere, reference outputs dt (= 0)
        #pragma unroll
        for (int i = 0; i < 16; i++) oslab[(q0 + i) * WW + col] = 0.0f;
    }
}

extern "C" void kernel_launch(void* const* d_in, const int* in_sizes, int n_in,
                              void* d_out, int out_size)
{
    const float* in = (const float*)d_in[0];
    float* out = (float*)d_out;

    int slices = in_sizes[0] / (HH * WW);   // 48 for the reference shapes
    if (slices > MAXSLICES) slices = MAXSLICES;

    // Pin max smem carveout: 6 CTAs/SM (6 x 16.9KB = 101.5KB) never smem-limited.
    cudaFuncSetAttribute(wdt_fused, cudaFuncAttributePreferredSharedMemoryCarveout, 100);

    k_pack<<<slices * 32, 256>>>(in);
    // launch_bounds(256,6): capacity 148*6 = 888 >= grid 768 -> all CTAs
    // co-resident -> the max rendezvous cannot deadlock.
    wdt_fused<<<slices * TPC, 256>>>(out);
}